// round 1
// baseline (speedup 1.0000x reference)
#include <cuda_runtime.h>
#include <math.h>

// ---------------------------------------------------------------------------
// HyperNetworkDecoder: K=2 scenes, P=4096 points, 8 layers of width 64.
// Key structural fact: the hypernetwork "chunk" input is constant across P,
// so per (k, layer) there is ONE generated weight matrix + bias. We generate
// them once (hyper_kernel) into __device__ scratch, then run the per-point
// MLP (decode_kernel) reading those weights via broadcast L1 loads.
// ---------------------------------------------------------------------------

#define KB 2
#define PN 4096

// scratch: generated weights/biases (allocation-free rule => __device__ globals)
__device__ __align__(16) float g_W0[KB * 64 * 128];      // layer0 W [k][n=64][m=128 (126 + 2 zero pad)]
__device__ __align__(16) float g_Wl[KB * 7 * 64 * 64];   // layers 1..7 W [k][l-1][n][m]
__device__ __align__(16) float g_b [KB * 8 * 64];        // biases [k][l][n]

// ---------------------------------------------------------------------------
// Kernel 1: hypernetwork. grid = (k,l) x 8 output-splits = 128 blocks.
// ---------------------------------------------------------------------------
__global__ void __launch_bounds__(256) hyper_kernel(
    const float* __restrict__ latent_tokens,   // (2,8,64)
    const float* __restrict__ token_embeddings,// (8,64)
    const float* __restrict__ h_W0,  const float* __restrict__ h_b0,
    const float* __restrict__ h_ln_s0, const float* __restrict__ h_ln_b0,
    const float* __restrict__ w_W0,  const float* __restrict__ w_b0,
    const float* __restrict__ bb_W0, const float* __restrict__ bb_b0,
    const float* __restrict__ h_W,   const float* __restrict__ h_b,
    const float* __restrict__ h_ln_s, const float* __restrict__ h_ln_b,
    const float* __restrict__ w_W,   const float* __restrict__ w_b,
    const float* __restrict__ bb_W,  const float* __restrict__ bb_b)
{
    __shared__ float chunk[128];
    __shared__ float part[4][64];
    __shared__ float pre[64];
    __shared__ float hbuf[64];

    const int tid = threadIdx.x;
    const int bx  = blockIdx.x;
    const int sp  = bx & 7;       // output split 0..7
    const int kl  = bx >> 3;
    const int k   = kl >> 3;
    const int l   = kl & 7;

    // chunk = [latent_tokens[k,l,:64], token_embeddings[l,:64]]
    if (tid < 128)
        chunk[tid] = (tid < 64) ? latent_tokens[(k * 8 + l) * 64 + tid]
                                : token_embeddings[l * 64 + (tid - 64)];
    __syncthreads();

    // h_pre = chunk @ hW + hb   (128x64), split over 4 thread groups
    const float* hWp = (l == 0) ? h_W0 : (h_W + (l - 1) * 128 * 64);
    {
        const int q = tid >> 6, j = tid & 63;
        float acc = 0.f;
        #pragma unroll
        for (int i = 0; i < 32; i++) {
            int ii = q * 32 + i;
            acc = fmaf(chunk[ii], __ldg(hWp + ii * 64 + j), acc);
        }
        part[q][j] = acc;
    }
    __syncthreads();
    if (tid < 64) {
        float hb = (l == 0) ? __ldg(h_b0 + tid) : __ldg(h_b + (l - 1) * 64 + tid);
        pre[tid] = part[0][tid] + part[1][tid] + part[2][tid] + part[3][tid] + hb;
    }
    __syncthreads();
    // h = relu(LN(h_pre))
    if (tid < 64) {
        float s1 = 0.f, s2 = 0.f;
        #pragma unroll 8
        for (int i = 0; i < 64; i++) { float v = pre[i]; s1 += v; s2 += v * v; }
        float mu   = s1 * (1.f / 64.f);
        float var  = s2 * (1.f / 64.f) - mu * mu;
        float rstd = rsqrtf(var + 1e-6f);
        float ls = (l == 0) ? __ldg(h_ln_s0 + tid) : __ldg(h_ln_s + (l - 1) * 64 + tid);
        float lb = (l == 0) ? __ldg(h_ln_b0 + tid) : __ldg(h_ln_b + (l - 1) * 64 + tid);
        float h  = fmaf((pre[tid] - mu) * rstd, ls, lb);
        hbuf[tid] = fmaxf(h, 0.f);
    }
    __syncthreads();

    // W = h @ wW + wb  -- this block's slice of the OUT dimension
    const int OUT  = (l == 0) ? 8064 : 4096;
    const int CH   = OUT >> 3;
    const int o0   = sp * CH, oend = o0 + CH;
    const float* wWp = (l == 0) ? w_W0 : (w_W + (l - 1) * 64 * 4096);
    const float* wbp = (l == 0) ? w_b0 : (w_b + (l - 1) * 4096);

    float acc[4];
    #pragma unroll
    for (int i = 0; i < 4; i++) {
        int o = o0 + tid + i * 256;
        acc[i] = (o < oend) ? __ldg(wbp + o) : 0.f;
    }
    #pragma unroll 4
    for (int j = 0; j < 64; j++) {
        float hj = hbuf[j];
        const float* row = wWp + j * OUT;
        #pragma unroll
        for (int i = 0; i < 4; i++) {
            int o = o0 + tid + i * 256;
            if (o < oend) acc[i] = fmaf(hj, __ldg(row + o), acc[i]);
        }
    }
    #pragma unroll
    for (int i = 0; i < 4; i++) {
        int o = o0 + tid + i * 256;
        if (o < oend) {
            if (l == 0) {                    // reshape (64, 126), pad rows to 128
                int n = o / 126, m = o - n * 126;
                g_W0[(k * 64 + n) * 128 + m] = acc[i];
            } else {
                g_Wl[(k * 7 + (l - 1)) * 4096 + o] = acc[i];
            }
        }
    }

    // bias b = h @ bbW + bb, plus zero-pad of g_W0 columns 126..127
    if (sp == 0 && tid < 64) {
        if (l == 0) {
            g_W0[(k * 64 + tid) * 128 + 126] = 0.f;
            g_W0[(k * 64 + tid) * 128 + 127] = 0.f;
        }
        const float* bWp = (l == 0) ? bb_W0 : (bb_W + (l - 1) * 64 * 64);
        float accb = (l == 0) ? __ldg(bb_b0 + tid) : __ldg(bb_b + (l - 1) * 64 + tid);
        #pragma unroll 8
        for (int j = 0; j < 64; j++)
            accb = fmaf(hbuf[j], __ldg(bWp + j * 64 + tid), accb);
        g_b[(k * 8 + l) * 64 + tid] = accb;
    }
}

// ---------------------------------------------------------------------------
// Accurate sin for large args (robust whether or not --use_fast_math maps
// sinf -> __sinf): double-precision range reduction, then small-arg sinf.
// ---------------------------------------------------------------------------
__device__ __forceinline__ float acc_sin(float x)
{
    double xd = (double)x;
    double q  = rint(xd * 0.31830988618379067154);     // x / pi
    double r  = fma(-q, 3.14159265358979323846, xd);   // |r| <= pi/2
    float  s  = sinf((float)r);
    return (((long long)q) & 1) ? -s : s;
}

#define FMA4(A, XX, WW) do { \
    A = fmaf((XX).x, (WW).x, A); A = fmaf((XX).y, (WW).y, A); \
    A = fmaf((XX).z, (WW).z, A); A = fmaf((XX).w, (WW).w, A); } while (0)

// One layer: y = x @ W^T + b ; LN ; relu.  Each thread handles 32 of the 64
// outputs for its point (n0 selects the half). W read via broadcast __ldg
// (all lanes same address -> one 16B sector, L1-resident).
template <int M4>
__device__ __forceinline__ void mac_ln(
    const float4* xv, const float* wbase, const float* bias,
    const float* lns, const float* lnb,
    float* xrow, float* red1, float* red2, int tid, int n0)
{
    float s1 = 0.f, s2 = 0.f;
    #pragma unroll 2
    for (int i = 0; i < 32; i++) {
        int n = n0 + i;
        const float4* wr = (const float4*)wbase + n * M4;
        float a0 = __ldg(bias + n), a1 = 0.f;
        #pragma unroll
        for (int m = 0; m < M4; m += 2) {
            float4 w0 = __ldg(wr + m), w1 = __ldg(wr + m + 1);
            FMA4(a0, xv[m],     w0);
            FMA4(a1, xv[m + 1], w1);
        }
        float y = a0 + a1;
        s1 += y; s2 += y * y;
        xrow[n] = y;                           // raw pre-LN value
    }
    red1[tid] = s1; red2[tid] = s2;
    __syncthreads();
    float mu   = (s1 + red1[tid ^ 64]) * (1.f / 64.f);
    float var  = (s2 + red2[tid ^ 64]) * (1.f / 64.f) - mu * mu;
    float rstd = rsqrtf(var + 1e-6f);
    #pragma unroll 4
    for (int i = 0; i < 32; i++) {
        int n = n0 + i;
        float v = xrow[n];
        v = fmaf((v - mu) * rstd, __ldg(lns + n), __ldg(lnb + n));
        xrow[n] = fmaxf(v, 0.f);
    }
}

// ---------------------------------------------------------------------------
// Kernel 2: per-point decoder. 128 blocks x 128 threads; each block owns 64
// points (all same k), each point served by 2 threads (output halves).
// x vector lives in registers; stride-132 smem row gives 4-phase-optimal
// LDS.128 when reloading x between layers.
// ---------------------------------------------------------------------------
__global__ void __launch_bounds__(128) decode_kernel(
    const float* __restrict__ rays,
    const float* __restrict__ ln_s0, const float* __restrict__ ln_b0,
    const float* __restrict__ ln_s,  const float* __restrict__ ln_b,
    const float* __restrict__ rgb_W, const float* __restrict__ rgb_b,
    float* __restrict__ out)
{
    __shared__ __align__(16) float xs[64 * 132];
    __shared__ float red1[128], red2[128];

    const int tid  = threadIdx.x;
    const int pt   = tid & 63, half = tid >> 6;
    const int n0   = half << 5;
    const int gpt  = blockIdx.x * 64 + pt;
    const int k    = blockIdx.x >> 6;
    float* xrow = xs + pt * 132;

    // ---- positional encoding (both halves split the 10 frequencies) ----
    {
        const float* r = rays + gpt * 6;
        float ox = r[0], oy = r[1], oz = r[2];
        float dx = r[3], dy = r[4], dz = r[5];
        float pl[6];
        pl[0] = dx; pl[1] = dy; pl[2] = dz;
        pl[3] = oy * dz - oz * dy;
        pl[4] = oz * dx - ox * dz;
        pl[5] = ox * dy - oy * dx;
        if (half == 0) {
            #pragma unroll
            for (int c = 0; c < 6; c++) xrow[c] = pl[c];
        } else {
            xrow[126] = 0.f; xrow[127] = 0.f;  // pad for 128-wide layer-0 dot
        }
        const float PIH = 1.57079632679489662f;
        const int f0 = half * 5;
        #pragma unroll
        for (int f = f0; f < f0 + 5; f++) {
            float fr = (float)(1 << f);
            #pragma unroll
            for (int c = 0; c < 6; c++) {
                float a = pl[c] * fr;
                xrow[6 + f * 6 + c]        = acc_sin(a);         // sin
                xrow[6 + (10 + f) * 6 + c] = acc_sin(a + PIH);   // sin(x+pi/2)
            }
        }
    }

    // ---- layer 0 (126-wide input, padded to 128) ----
    __syncthreads();
    {
        float4 xv[32];
        const float4* xr4 = (const float4*)xrow;
        #pragma unroll
        for (int i = 0; i < 32; i++) xv[i] = xr4[i];
        __syncthreads();   // everyone captured x before xrow gets overwritten
        mac_ln<32>(xv, g_W0 + k * 8192, g_b + k * 512,
                   ln_s0, ln_b0, xrow, red1, red2, tid, n0);
    }

    // ---- layers 1..7 (64-wide) ----
    for (int l = 1; l < 8; l++) {
        __syncthreads();   // partner's LN writes visible
        float4 xv[16];
        const float4* xr4 = (const float4*)xrow;
        #pragma unroll
        for (int i = 0; i < 16; i++) xv[i] = xr4[i];
        __syncthreads();
        mac_ln<16>(xv, g_Wl + (k * 7 + (l - 1)) * 4096, g_b + k * 512 + l * 64,
                   ln_s + (l - 1) * 64, ln_b + (l - 1) * 64,
                   xrow, red1, red2, tid, n0);
    }

    // ---- rgb head + sigmoid ----
    __syncthreads();
    if (half == 0) {
        float a0 = __ldg(rgb_b + 0), a1 = __ldg(rgb_b + 1), a2 = __ldg(rgb_b + 2);
        #pragma unroll 8
        for (int m = 0; m < 64; m++) {
            float v = xrow[m];
            a0 = fmaf(v, __ldg(rgb_W + m * 3 + 0), a0);
            a1 = fmaf(v, __ldg(rgb_W + m * 3 + 1), a1);
            a2 = fmaf(v, __ldg(rgb_W + m * 3 + 2), a2);
        }
        float* op = out + gpt * 3;
        op[0] = 1.f / (1.f + expf(-a0));
        op[1] = 1.f / (1.f + expf(-a1));
        op[2] = 1.f / (1.f + expf(-a2));
    }
}

// ---------------------------------------------------------------------------
extern "C" void kernel_launch(void* const* d_in, const int* in_sizes, int n_in,
                              void* d_out, int out_size)
{
    const float* rays    = (const float*)d_in[0];
    const float* lat     = (const float*)d_in[1];
    const float* temb    = (const float*)d_in[2];
    const float* h_W0    = (const float*)d_in[3];
    const float* h_b0    = (const float*)d_in[4];
    const float* h_ln_s0 = (const float*)d_in[5];
    const float* h_ln_b0 = (const float*)d_in[6];
    const float* w_W0    = (const float*)d_in[7];
    const float* w_b0    = (const float*)d_in[8];
    const float* bb_W0   = (const float*)d_in[9];
    const float* bb_b0   = (const float*)d_in[10];
    const float* ln_s0   = (const float*)d_in[11];
    const float* ln_b0   = (const float*)d_in[12];
    const float* h_W     = (const float*)d_in[13];
    const float* h_b     = (const float*)d_in[14];
    const float* h_ln_s  = (const float*)d_in[15];
    const float* h_ln_b  = (const float*)d_in[16];
    const float* w_W     = (const float*)d_in[17];
    const float* w_b     = (const float*)d_in[18];
    const float* bb_W    = (const float*)d_in[19];
    const float* bb_b    = (const float*)d_in[20];
    const float* ln_s    = (const float*)d_in[21];
    const float* ln_b    = (const float*)d_in[22];
    const float* rgb_W   = (const float*)d_in[23];
    const float* rgb_b   = (const float*)d_in[24];
    float* out = (float*)d_out;

    hyper_kernel<<<128, 256>>>(lat, temb, h_W0, h_b0, h_ln_s0, h_ln_b0,
                               w_W0, w_b0, bb_W0, bb_b0,
                               h_W, h_b, h_ln_s, h_ln_b,
                               w_W, w_b, bb_W, bb_b);
    decode_kernel<<<128, 128>>>(rays, ln_s0, ln_b0, ln_s, ln_b,
                                rgb_W, rgb_b, out);
}

// round 2
// speedup vs baseline: 3.3286x; 3.3286x over previous
#include <cuda_runtime.h>
#include <math.h>

// ---------------------------------------------------------------------------
// HyperNetworkDecoder: K=2 scenes, P=4096 points, 8 layers of width 64.
// hyper_kernel: generate per-(k,layer) weight matrices once (chunk is constant
// across P).  decode_kernel: per-point MLP, 8 threads per point, weights
// staged through shared memory with a register double-buffer.
// ---------------------------------------------------------------------------

#define KB 2

__device__ __align__(16) float g_W0[KB * 64 * 128];      // layer0 W [k][n][m pad128]
__device__ __align__(16) float g_Wl[KB * 7 * 64 * 64];   // layers 1..7 [k][l-1][n][m]
__device__ __align__(16) float g_b [KB * 8 * 64];        // biases [k][l][n]

// ---------------------------------------------------------------------------
// Kernel 1: hypernetwork (unchanged from R1 — small cost, HBM-stream bound).
// ---------------------------------------------------------------------------
__global__ void __launch_bounds__(256) hyper_kernel(
    const float* __restrict__ latent_tokens,
    const float* __restrict__ token_embeddings,
    const float* __restrict__ h_W0,  const float* __restrict__ h_b0,
    const float* __restrict__ h_ln_s0, const float* __restrict__ h_ln_b0,
    const float* __restrict__ w_W0,  const float* __restrict__ w_b0,
    const float* __restrict__ bb_W0, const float* __restrict__ bb_b0,
    const float* __restrict__ h_W,   const float* __restrict__ h_b,
    const float* __restrict__ h_ln_s, const float* __restrict__ h_ln_b,
    const float* __restrict__ w_W,   const float* __restrict__ w_b,
    const float* __restrict__ bb_W,  const float* __restrict__ bb_b)
{
    __shared__ float chunk[128];
    __shared__ float part[4][64];
    __shared__ float pre[64];
    __shared__ float hbuf[64];

    const int tid = threadIdx.x;
    const int bx  = blockIdx.x;
    const int sp  = bx & 7;
    const int kl  = bx >> 3;
    const int k   = kl >> 3;
    const int l   = kl & 7;

    if (tid < 128)
        chunk[tid] = (tid < 64) ? latent_tokens[(k * 8 + l) * 64 + tid]
                                : token_embeddings[l * 64 + (tid - 64)];
    __syncthreads();

    const float* hWp = (l == 0) ? h_W0 : (h_W + (l - 1) * 128 * 64);
    {
        const int q = tid >> 6, j = tid & 63;
        float acc = 0.f;
        #pragma unroll
        for (int i = 0; i < 32; i++) {
            int ii = q * 32 + i;
            acc = fmaf(chunk[ii], __ldg(hWp + ii * 64 + j), acc);
        }
        part[q][j] = acc;
    }
    __syncthreads();
    if (tid < 64) {
        float hb = (l == 0) ? __ldg(h_b0 + tid) : __ldg(h_b + (l - 1) * 64 + tid);
        pre[tid] = part[0][tid] + part[1][tid] + part[2][tid] + part[3][tid] + hb;
    }
    __syncthreads();
    if (tid < 64) {
        float s1 = 0.f, s2 = 0.f;
        #pragma unroll 8
        for (int i = 0; i < 64; i++) { float v = pre[i]; s1 += v; s2 += v * v; }
        float mu   = s1 * (1.f / 64.f);
        float var  = s2 * (1.f / 64.f) - mu * mu;
        float rstd = rsqrtf(var + 1e-6f);
        float ls = (l == 0) ? __ldg(h_ln_s0 + tid) : __ldg(h_ln_s + (l - 1) * 64 + tid);
        float lb = (l == 0) ? __ldg(h_ln_b0 + tid) : __ldg(h_ln_b + (l - 1) * 64 + tid);
        float h  = fmaf((pre[tid] - mu) * rstd, ls, lb);
        hbuf[tid] = fmaxf(h, 0.f);
    }
    __syncthreads();

    const int OUT  = (l == 0) ? 8064 : 4096;
    const int CH   = OUT >> 3;
    const int o0   = sp * CH, oend = o0 + CH;
    const float* wWp = (l == 0) ? w_W0 : (w_W + (l - 1) * 64 * 4096);
    const float* wbp = (l == 0) ? w_b0 : (w_b + (l - 1) * 4096);

    float acc[4];
    #pragma unroll
    for (int i = 0; i < 4; i++) {
        int o = o0 + tid + i * 256;
        acc[i] = (o < oend) ? __ldg(wbp + o) : 0.f;
    }
    #pragma unroll 4
    for (int j = 0; j < 64; j++) {
        float hj = hbuf[j];
        const float* row = wWp + j * OUT;
        #pragma unroll
        for (int i = 0; i < 4; i++) {
            int o = o0 + tid + i * 256;
            if (o < oend) acc[i] = fmaf(hj, __ldg(row + o), acc[i]);
        }
    }
    #pragma unroll
    for (int i = 0; i < 4; i++) {
        int o = o0 + tid + i * 256;
        if (o < oend) {
            if (l == 0) {
                int n = o / 126, m = o - n * 126;
                g_W0[(k * 64 + n) * 128 + m] = acc[i];
            } else {
                g_Wl[(k * 7 + (l - 1)) * 4096 + o] = acc[i];
            }
        }
    }

    if (sp == 0 && tid < 64) {
        if (l == 0) {
            g_W0[(k * 64 + tid) * 128 + 126] = 0.f;
            g_W0[(k * 64 + tid) * 128 + 127] = 0.f;
        }
        const float* bWp = (l == 0) ? bb_W0 : (bb_W + (l - 1) * 64 * 64);
        float accb = (l == 0) ? __ldg(bb_b0 + tid) : __ldg(bb_b + (l - 1) * 64 + tid);
        #pragma unroll 8
        for (int j = 0; j < 64; j++)
            accb = fmaf(hbuf[j], __ldg(bWp + j * 64 + tid), accb);
        g_b[(k * 8 + l) * 64 + tid] = accb;
    }
}

// ---------------------------------------------------------------------------
// Float-only accurate sin: 2-term Cody-Waite reduction by pi, then sinf on
// |r| <= pi/2.  Max arg ~2500 rad -> q ~ 800, residual ~1e-12, total ~1e-7.
// ---------------------------------------------------------------------------
__device__ __forceinline__ float acc_sin(float x)
{
    float q = rintf(x * 0.318309886183790672f);
    float r = fmaf(-q, 3.14159274101257324f, x);     // pi_hi (fl(pi))
    r = fmaf(-q, -8.74227800037e-8f, r);             // pi_lo = pi - pi_hi
    float s = sinf(r);
    return (((int)q) & 1) ? -s : s;
}

#define FMA4(A, XX, WW) do { \
    A = fmaf((XX).x, (WW).x, A); A = fmaf((XX).y, (WW).y, A); \
    A = fmaf((XX).z, (WW).z, A); A = fmaf((XX).w, (WW).w, A); } while (0)

// ---------------------------------------------------------------------------
// Kernel 2: decoder. 128 blocks x 512 threads (one wave). Block owns 64
// points (single k). Thread (w = tid>>6, p = tid&63): outputs [8w, 8w+8)
// of point p.  x rows in smem (stride 132 floats -> conflict-free LDS.128),
// W in smem double buffer (broadcast LDS), next stage prefetched into regs.
// ---------------------------------------------------------------------------
__global__ void __launch_bounds__(512) decode_kernel(
    const float* __restrict__ rays,
    const float* __restrict__ ln_s0, const float* __restrict__ ln_b0,
    const float* __restrict__ ln_s,  const float* __restrict__ ln_b,
    const float* __restrict__ rgb_W, const float* __restrict__ rgb_b,
    float* __restrict__ out)
{
    extern __shared__ float smem[];
    float*  xs   = smem;                               // 64 * 132 floats
    float4* wbuf = (float4*)(smem + 64 * 132);         // 2 x 1024 float4 (2x16KB)
    float*  red1 = smem + 64 * 132 + 8192;             // 512
    float*  red2 = red1 + 512;                         // 512

    const int tid = threadIdx.x;
    const int w   = tid >> 6;          // output group 0..7
    const int p   = tid & 63;          // point in block
    const int n0  = w * 8;
    const int gpt = blockIdx.x * 64 + p;
    const int k   = blockIdx.x >> 6;

    float*        xrow  = xs + p * 132;
    const float4* xrow4 = (const float4*)xrow;

    const float4* W0v = (const float4*)g_W0 + k * 2048;   // [64][32] f4
    const float4* Wlv = (const float4*)g_Wl + k * 7 * 1024;
    const float*  bb  = g_b + k * 512;

    float4 pre0, pre1;
    // stage s: 0,1 = W0 halves; 2..8 = layers 1..7
    auto ldStage = [&](int s) {
        if (s < 2) {
            int d0 = tid, d1 = tid + 512;
            pre0 = __ldg(W0v + (d0 >> 4) * 32 + s * 16 + (d0 & 15));
            pre1 = __ldg(W0v + (d1 >> 4) * 32 + s * 16 + (d1 & 15));
        } else {
            const float4* src = Wlv + (s - 2) * 1024;
            pre0 = __ldg(src + tid);
            pre1 = __ldg(src + tid + 512);
        }
    };
    auto stStage = [&](float4* b) { b[tid] = pre0; b[tid + 512] = pre1; };

    // ---- prologue: prefetch stage0, posenc, store stage0, prefetch stage1 ----
    ldStage(0);
    {
        const float* r = rays + gpt * 6;
        float ox = r[0], oy = r[1], oz = r[2];
        float dx = r[3], dy = r[4], dz = r[5];
        float pl[6];
        pl[0] = dx; pl[1] = dy; pl[2] = dz;
        pl[3] = oy * dz - oz * dy;
        pl[4] = oz * dx - ox * dz;
        pl[5] = ox * dy - oy * dx;
        if (w == 6) {
            #pragma unroll
            for (int c = 0; c < 6; c++) xrow[c] = pl[c];
        }
        if (w == 7) { xrow[126] = 0.f; xrow[127] = 0.f; }
        const float PIH = 1.57079632679489662f;
        for (int f = w; f < 10; f += 8) {
            float fr = (float)(1 << f);
            #pragma unroll
            for (int c = 0; c < 6; c++) {
                float a = pl[c] * fr;
                xrow[6 + f * 6 + c]      = acc_sin(a);
                xrow[66 + f * 6 + c]     = acc_sin(a + PIH);
            }
        }
    }
    stStage(wbuf);            // stage0 -> buf0
    ldStage(1);
    __syncthreads();          // S0: buf0 + posenc visible

    float acc[8];
    #pragma unroll
    for (int j = 0; j < 8; j++) acc[j] = __ldg(bb + n0 + j);

    // ---- layer0 half 0 (m4 0..15 from buf0) ----
    stStage(wbuf + 1024);     // stage1 -> buf1 (no readers yet)
    ldStage(2);
    #pragma unroll
    for (int m4 = 0; m4 < 16; m4++) {
        float4 xv = xrow4[m4];
        #pragma unroll
        for (int j = 0; j < 8; j++) FMA4(acc[j], xv, wbuf[(n0 + j) * 16 + m4]);
    }
    __syncthreads();          // S1: buf1 visible; buf0 free

    // ---- layer0 half 1 (m4 16..31 from buf1) ----
    stStage(wbuf);            // stage2 -> buf0
    ldStage(3);
    {
        const float4* B = wbuf + 1024;
        #pragma unroll
        for (int m4 = 0; m4 < 16; m4++) {
            float4 xv = xrow4[16 + m4];
            #pragma unroll
            for (int j = 0; j < 8; j++) FMA4(acc[j], xv, B[(n0 + j) * 16 + m4]);
        }
    }

    // ---- per-layer LN + relu + writeback, then layers 1..7 ----
    for (int l = 0; l < 8; l++) {
        if (l > 0) {
            // prefetched store for stage l+2 happens below (pre regs hold it)
            const float4* B = wbuf + ((l + 1) & 1) * 1024;
            #pragma unroll
            for (int j = 0; j < 8; j++) acc[j] = __ldg(bb + l * 64 + n0 + j);
            #pragma unroll
            for (int m4 = 0; m4 < 16; m4++) {
                float4 xv = xrow4[m4];
                #pragma unroll
                for (int j = 0; j < 8; j++) FMA4(acc[j], xv, B[(n0 + j) * 16 + m4]);
            }
        }
        // LN partial sums
        float s1 = 0.f, s2 = 0.f;
        #pragma unroll
        for (int j = 0; j < 8; j++) { s1 += acc[j]; s2 += acc[j] * acc[j]; }
        red1[w * 64 + p] = s1;
        red2[w * 64 + p] = s2;
        __syncthreads();      // A: partials ready, this layer's x reads done
        float S1 = 0.f, S2 = 0.f;
        #pragma unroll
        for (int j = 0; j < 8; j++) { S1 += red1[j * 64 + p]; S2 += red2[j * 64 + p]; }
        float mu   = S1 * (1.f / 64.f);
        float var  = S2 * (1.f / 64.f) - mu * mu;
        float rstd = rsqrtf(var + 1e-6f);
        const float* lns = (l == 0) ? ln_s0 : (ln_s + (l - 1) * 64);
        const float* lnb = (l == 0) ? ln_b0 : (ln_b + (l - 1) * 64);
        #pragma unroll
        for (int j = 0; j < 8; j++) {
            float v = fmaf((acc[j] - mu) * rstd, __ldg(lns + n0 + j), __ldg(lnb + n0 + j));
            acc[j] = fmaxf(v, 0.f);
        }
        // write x for next layer (2 x STS.128)
        float4 o0 = make_float4(acc[0], acc[1], acc[2], acc[3]);
        float4 o1 = make_float4(acc[4], acc[5], acc[6], acc[7]);
        ((float4*)xrow)[2 * w]     = o0;
        ((float4*)xrow)[2 * w + 1] = o1;
        // store prefetched stage l+3 -> its buffer; prefetch stage l+4
        if (l < 6) {
            stStage(wbuf + ((l + 1) & 1) * 1024);   // stage l+3 -> buf[(l+3)&1] == buf[(l+1)&1]
            if (l + 4 <= 8) ldStage(l + 4);
        }
        __syncthreads();      // B: xs + next W buffer visible
    }

    // ---- rgb head + sigmoid (3 of 8 groups active) ----
    if (w < 3) {
        float a = __ldg(rgb_b + w);
        #pragma unroll
        for (int m4 = 0; m4 < 16; m4++) {
            float4 xv = xrow4[m4];
            a = fmaf(xv.x, __ldg(rgb_W + (m4 * 4 + 0) * 3 + w), a);
            a = fmaf(xv.y, __ldg(rgb_W + (m4 * 4 + 1) * 3 + w), a);
            a = fmaf(xv.z, __ldg(rgb_W + (m4 * 4 + 2) * 3 + w), a);
            a = fmaf(xv.w, __ldg(rgb_W + (m4 * 4 + 3) * 3 + w), a);
        }
        out[gpt * 3 + w] = 1.f / (1.f + expf(-a));
    }
}

// ---------------------------------------------------------------------------
extern "C" void kernel_launch(void* const* d_in, const int* in_sizes, int n_in,
                              void* d_out, int out_size)
{
    const float* rays    = (const float*)d_in[0];
    const float* lat     = (const float*)d_in[1];
    const float* temb    = (const float*)d_in[2];
    const float* h_W0    = (const float*)d_in[3];
    const float* h_b0    = (const float*)d_in[4];
    const float* h_ln_s0 = (const float*)d_in[5];
    const float* h_ln_b0 = (const float*)d_in[6];
    const float* w_W0    = (const float*)d_in[7];
    const float* w_b0    = (const float*)d_in[8];
    const float* bb_W0   = (const float*)d_in[9];
    const float* bb_b0   = (const float*)d_in[10];
    const float* ln_s0   = (const float*)d_in[11];
    const float* ln_b0   = (const float*)d_in[12];
    const float* h_W     = (const float*)d_in[13];
    const float* h_b     = (const float*)d_in[14];
    const float* h_ln_s  = (const float*)d_in[15];
    const float* h_ln_b  = (const float*)d_in[16];
    const float* w_W     = (const float*)d_in[17];
    const float* w_b     = (const float*)d_in[18];
    const float* bb_W    = (const float*)d_in[19];
    const float* bb_b    = (const float*)d_in[20];
    const float* ln_s    = (const float*)d_in[21];
    const float* ln_b    = (const float*)d_in[22];
    const float* rgb_W   = (const float*)d_in[23];
    const float* rgb_b   = (const float*)d_in[24];
    float* out = (float*)d_out;

    const int SMEM = 64 * 132 * 4 + 2 * 16384 + 2 * 512 * 4;   // 70656 B
    cudaFuncSetAttribute(decode_kernel,
                         cudaFuncAttributeMaxDynamicSharedMemorySize, SMEM);

    hyper_kernel<<<128, 256>>>(lat, temb, h_W0, h_b0, h_ln_s0, h_ln_b0,
                               w_W0, w_b0, bb_W0, bb_b0,
                               h_W, h_b, h_ln_s, h_ln_b,
                               w_W, w_b, bb_W, bb_b);
    decode_kernel<<<128, 512, SMEM>>>(rays, ln_s0, ln_b0, ln_s, ln_b,
                                      rgb_W, rgb_b, out);
}

// round 3
// speedup vs baseline: 3.5869x; 1.0776x over previous
#include <cuda_runtime.h>
#include <math.h>

// ---------------------------------------------------------------------------
// HyperNetworkDecoder: K=2 scenes, P=4096 points, 8 layers of width 64.
// hyper_kernel: generate per-(k,layer) weight matrices once (chunk constant
// across P).  decode_kernel: per-point MLP; 256-thread blocks (32 points x
// 8 threads/point) so 2-3 blocks co-reside per SM and barriers overlap.
// ---------------------------------------------------------------------------

#define KB 2

__device__ __align__(16) float g_W0[KB * 64 * 128];      // layer0 W [k][n][m pad128]
__device__ __align__(16) float g_Wl[KB * 7 * 64 * 64];   // layers 1..7 [k][l-1][n][m]
__device__ __align__(16) float g_b [KB * 8 * 64];        // biases [k][l][n]

// ---------------------------------------------------------------------------
// Kernel 1: hypernetwork. grid = (k,l) x 16 output-splits = 256 blocks.
// ---------------------------------------------------------------------------
__global__ void __launch_bounds__(256) hyper_kernel(
    const float* __restrict__ latent_tokens,
    const float* __restrict__ token_embeddings,
    const float* __restrict__ h_W0,  const float* __restrict__ h_b0,
    const float* __restrict__ h_ln_s0, const float* __restrict__ h_ln_b0,
    const float* __restrict__ w_W0,  const float* __restrict__ w_b0,
    const float* __restrict__ bb_W0, const float* __restrict__ bb_b0,
    const float* __restrict__ h_W,   const float* __restrict__ h_b,
    const float* __restrict__ h_ln_s, const float* __restrict__ h_ln_b,
    const float* __restrict__ w_W,   const float* __restrict__ w_b,
    const float* __restrict__ bb_W,  const float* __restrict__ bb_b)
{
    __shared__ float chunk[128];
    __shared__ float part[4][64];
    __shared__ float pre[64];
    __shared__ float hbuf[64];

    const int tid = threadIdx.x;
    const int bx  = blockIdx.x;
    const int sp  = bx & 15;      // output split 0..15
    const int kl  = bx >> 4;
    const int k   = kl >> 3;
    const int l   = kl & 7;

    if (tid < 128)
        chunk[tid] = (tid < 64) ? latent_tokens[(k * 8 + l) * 64 + tid]
                                : token_embeddings[l * 64 + (tid - 64)];
    __syncthreads();

    const float* hWp = (l == 0) ? h_W0 : (h_W + (l - 1) * 128 * 64);
    {
        const int q = tid >> 6, j = tid & 63;
        float acc = 0.f;
        #pragma unroll
        for (int i = 0; i < 32; i++) {
            int ii = q * 32 + i;
            acc = fmaf(chunk[ii], __ldg(hWp + ii * 64 + j), acc);
        }
        part[q][j] = acc;
    }
    __syncthreads();
    if (tid < 64) {
        float hb = (l == 0) ? __ldg(h_b0 + tid) : __ldg(h_b + (l - 1) * 64 + tid);
        pre[tid] = part[0][tid] + part[1][tid] + part[2][tid] + part[3][tid] + hb;
    }
    __syncthreads();
    if (tid < 64) {
        float s1 = 0.f, s2 = 0.f;
        #pragma unroll 8
        for (int i = 0; i < 64; i++) { float v = pre[i]; s1 += v; s2 += v * v; }
        float mu   = s1 * (1.f / 64.f);
        float var  = s2 * (1.f / 64.f) - mu * mu;
        float rstd = rsqrtf(var + 1e-6f);
        float ls = (l == 0) ? __ldg(h_ln_s0 + tid) : __ldg(h_ln_s + (l - 1) * 64 + tid);
        float lb = (l == 0) ? __ldg(h_ln_b0 + tid) : __ldg(h_ln_b + (l - 1) * 64 + tid);
        float h  = fmaf((pre[tid] - mu) * rstd, ls, lb);
        hbuf[tid] = fmaxf(h, 0.f);
    }
    __syncthreads();

    const int OUT  = (l == 0) ? 8064 : 4096;
    const int CH   = OUT >> 4;                // per-split outputs (504 or 256)
    const int o0   = sp * CH, oend = o0 + CH;
    const float* wWp = (l == 0) ? w_W0 : (w_W + (l - 1) * 64 * 4096);
    const float* wbp = (l == 0) ? w_b0 : (w_b + (l - 1) * 4096);

    float acc[2];
    #pragma unroll
    for (int i = 0; i < 2; i++) {
        int o = o0 + tid + i * 256;
        acc[i] = (o < oend) ? __ldg(wbp + o) : 0.f;
    }
    #pragma unroll 8
    for (int j = 0; j < 64; j++) {
        float hj = hbuf[j];
        const float* row = wWp + j * OUT;
        #pragma unroll
        for (int i = 0; i < 2; i++) {
            int o = o0 + tid + i * 256;
            if (o < oend) acc[i] = fmaf(hj, __ldg(row + o), acc[i]);
        }
    }
    #pragma unroll
    for (int i = 0; i < 2; i++) {
        int o = o0 + tid + i * 256;
        if (o < oend) {
            if (l == 0) {
                int n = o / 126, m = o - n * 126;
                g_W0[(k * 64 + n) * 128 + m] = acc[i];
            } else {
                g_Wl[(k * 7 + (l - 1)) * 4096 + o] = acc[i];
            }
        }
    }

    if (sp == 0 && tid < 64) {
        if (l == 0) {
            g_W0[(k * 64 + tid) * 128 + 126] = 0.f;
            g_W0[(k * 64 + tid) * 128 + 127] = 0.f;
        }
        const float* bWp = (l == 0) ? bb_W0 : (bb_W + (l - 1) * 64 * 64);
        float accb = (l == 0) ? __ldg(bb_b0 + tid) : __ldg(bb_b + (l - 1) * 64 + tid);
        #pragma unroll 8
        for (int j = 0; j < 64; j++)
            accb = fmaf(hbuf[j], __ldg(bWp + j * 64 + tid), accb);
        g_b[(k * 8 + l) * 64 + tid] = accb;
    }
}

// ---------------------------------------------------------------------------
// Float-only accurate sin: 2-term Cody-Waite reduction by pi, then sinf.
// ---------------------------------------------------------------------------
__device__ __forceinline__ float acc_sin(float x)
{
    float q = rintf(x * 0.318309886183790672f);
    float r = fmaf(-q, 3.14159274101257324f, x);     // pi_hi
    r = fmaf(-q, -8.74227800037e-8f, r);             // pi_lo
    float s = sinf(r);
    return (((int)q) & 1) ? -s : s;
}

#define FMA4(A, XX, WW) do { \
    A = fmaf((XX).x, (WW).x, A); A = fmaf((XX).y, (WW).y, A); \
    A = fmaf((XX).z, (WW).z, A); A = fmaf((XX).w, (WW).w, A); } while (0)

// ---------------------------------------------------------------------------
// Kernel 2: decoder. 256 blocks x 256 threads. Block owns 32 points (one k);
// thread (w = tid>>5, p = tid&31) computes outputs [8w, 8w+8) of point p.
// x rows in smem (stride-132 -> conflict-free LDS.128); W double-buffered in
// smem with register prefetch of the next stage.
// ---------------------------------------------------------------------------
__global__ void __launch_bounds__(256, 3) decode_kernel(
    const float* __restrict__ rays,
    const float* __restrict__ ln_s0, const float* __restrict__ ln_b0,
    const float* __restrict__ ln_s,  const float* __restrict__ ln_b,
    const float* __restrict__ rgb_W, const float* __restrict__ rgb_b,
    float* __restrict__ out)
{
    extern __shared__ float smem[];
    float*  xs   = smem;                               // 32 * 132 floats
    float4* wbuf = (float4*)(smem + 32 * 132);         // 2 x 1024 float4
    float2* red  = (float2*)(smem + 32 * 132 + 8192);  // 256 float2

    const int tid = threadIdx.x;
    const int w   = tid >> 5;          // output group 0..7
    const int p   = tid & 31;          // point in block
    const int n0  = w * 8;
    const int gpt = blockIdx.x * 32 + p;
    const int k   = blockIdx.x >> 7;

    float*        xrow  = xs + p * 132;
    const float4* xrow4 = (const float4*)xrow;

    const float4* W0v = (const float4*)g_W0 + k * 2048;   // [64][32] f4
    const float4* Wlv = (const float4*)g_Wl + k * 7 * 1024;
    const float*  bb  = g_b + k * 512;

    float4 pre[4];
    // stage s: 0,1 = W0 halves; 2..8 = layers 1..7. Each stage = 1024 float4.
    auto ldStage = [&](int s) {
        #pragma unroll
        for (int i = 0; i < 4; i++) {
            int idx = tid + i * 256;
            if (s < 2)
                pre[i] = __ldg(W0v + (idx >> 4) * 32 + s * 16 + (idx & 15));
            else
                pre[i] = __ldg(Wlv + (s - 2) * 1024 + idx);
        }
    };
    auto stStage = [&](float4* b) {
        #pragma unroll
        for (int i = 0; i < 4; i++) b[tid + i * 256] = pre[i];
    };

    // ---- prologue: prefetch stage0, posenc, store stage0, prefetch stage1 ----
    ldStage(0);
    {
        const float* r = rays + gpt * 6;
        float ox = r[0], oy = r[1], oz = r[2];
        float dx = r[3], dy = r[4], dz = r[5];
        float pl[6];
        pl[0] = dx; pl[1] = dy; pl[2] = dz;
        pl[3] = oy * dz - oz * dy;
        pl[4] = oz * dx - ox * dz;
        pl[5] = ox * dy - oy * dx;
        if (w == 6) {
            #pragma unroll
            for (int c = 0; c < 6; c++) xrow[c] = pl[c];
        }
        if (w == 7) { xrow[126] = 0.f; xrow[127] = 0.f; }
        const float PIH = 1.57079632679489662f;
        for (int f = w; f < 10; f += 8) {
            float fr = (float)(1 << f);
            #pragma unroll
            for (int c = 0; c < 6; c++) {
                float a = pl[c] * fr;
                xrow[6 + f * 6 + c]  = acc_sin(a);
                xrow[66 + f * 6 + c] = acc_sin(a + PIH);
            }
        }
    }
    stStage(wbuf);            // stage0 -> buf0
    ldStage(1);
    __syncthreads();          // buf0 + posenc visible

    float acc[8];
    #pragma unroll
    for (int j = 0; j < 8; j++) acc[j] = __ldg(bb + n0 + j);

    // ---- layer0 half 0 (m4 0..15 from buf0) ----
    stStage(wbuf + 1024);     // stage1 -> buf1
    ldStage(2);
    #pragma unroll
    for (int m4 = 0; m4 < 16; m4++) {
        float4 xv = xrow4[m4];
        #pragma unroll
        for (int j = 0; j < 8; j++) FMA4(acc[j], xv, wbuf[(n0 + j) * 16 + m4]);
    }
    __syncthreads();          // buf1 visible; buf0 free

    // ---- layer0 half 1 (m4 16..31 from buf1) ----
    stStage(wbuf);            // stage2 -> buf0
    ldStage(3);
    {
        const float4* B = wbuf + 1024;
        #pragma unroll
        for (int m4 = 0; m4 < 16; m4++) {
            float4 xv = xrow4[16 + m4];
            #pragma unroll
            for (int j = 0; j < 8; j++) FMA4(acc[j], xv, B[(n0 + j) * 16 + m4]);
        }
    }

    // ---- per-layer LN + relu + writeback, then layers 1..7 ----
    for (int l = 0; l < 8; l++) {
        if (l > 0) {
            const float4* B = wbuf + ((l + 1) & 1) * 1024;
            #pragma unroll
            for (int j = 0; j < 8; j++) acc[j] = __ldg(bb + l * 64 + n0 + j);
            #pragma unroll
            for (int m4 = 0; m4 < 16; m4++) {
                float4 xv = xrow4[m4];
                #pragma unroll
                for (int j = 0; j < 8; j++) FMA4(acc[j], xv, B[(n0 + j) * 16 + m4]);
            }
        }
        float s1 = 0.f, s2 = 0.f;
        #pragma unroll
        for (int j = 0; j < 8; j++) { s1 += acc[j]; s2 += acc[j] * acc[j]; }
        red[w * 32 + p] = make_float2(s1, s2);
        __syncthreads();      // partials ready; this layer's x reads done
        float S1 = 0.f, S2 = 0.f;
        #pragma unroll
        for (int j = 0; j < 8; j++) {
            float2 v = red[j * 32 + p];
            S1 += v.x; S2 += v.y;
        }
        float mu   = S1 * (1.f / 64.f);
        float var  = S2 * (1.f / 64.f) - mu * mu;
        float rstd = rsqrtf(var + 1e-6f);
        const float* lns = (l == 0) ? ln_s0 : (ln_s + (l - 1) * 64);
        const float* lnb = (l == 0) ? ln_b0 : (ln_b + (l - 1) * 64);
        #pragma unroll
        for (int j = 0; j < 8; j++) {
            float v = fmaf((acc[j] - mu) * rstd, __ldg(lns + n0 + j), __ldg(lnb + n0 + j));
            acc[j] = fmaxf(v, 0.f);
        }
        ((float4*)xrow)[2 * w]     = make_float4(acc[0], acc[1], acc[2], acc[3]);
        ((float4*)xrow)[2 * w + 1] = make_float4(acc[4], acc[5], acc[6], acc[7]);
        if (l < 6) {
            stStage(wbuf + ((l + 1) & 1) * 1024);   // stage l+3 -> buf[(l+3)&1]
            if (l + 4 <= 8) ldStage(l + 4);
        }
        __syncthreads();      // xs + next W buffer visible
    }

    // ---- rgb head + sigmoid (3 of 8 groups active) ----
    if (w < 3) {
        float a = __ldg(rgb_b + w);
        #pragma unroll
        for (int m4 = 0; m4 < 16; m4++) {
            float4 xv = xrow4[m4];
            a = fmaf(xv.x, __ldg(rgb_W + (m4 * 4 + 0) * 3 + w), a);
            a = fmaf(xv.y, __ldg(rgb_W + (m4 * 4 + 1) * 3 + w), a);
            a = fmaf(xv.z, __ldg(rgb_W + (m4 * 4 + 2) * 3 + w), a);
            a = fmaf(xv.w, __ldg(rgb_W + (m4 * 4 + 3) * 3 + w), a);
        }
        out[gpt * 3 + w] = 1.f / (1.f + expf(-a));
    }
}

// ---------------------------------------------------------------------------
extern "C" void kernel_launch(void* const* d_in, const int* in_sizes, int n_in,
                              void* d_out, int out_size)
{
    const float* rays    = (const float*)d_in[0];
    const float* lat     = (const float*)d_in[1];
    const float* temb    = (const float*)d_in[2];
    const float* h_W0    = (const float*)d_in[3];
    const float* h_b0    = (const float*)d_in[4];
    const float* h_ln_s0 = (const float*)d_in[5];
    const float* h_ln_b0 = (const float*)d_in[6];
    const float* w_W0    = (const float*)d_in[7];
    const float* w_b0    = (const float*)d_in[8];
    const float* bb_W0   = (const float*)d_in[9];
    const float* bb_b0   = (const float*)d_in[10];
    const float* ln_s0   = (const float*)d_in[11];
    const float* ln_b0   = (const float*)d_in[12];
    const float* h_W     = (const float*)d_in[13];
    const float* h_b     = (const float*)d_in[14];
    const float* h_ln_s  = (const float*)d_in[15];
    const float* h_ln_b  = (const float*)d_in[16];
    const float* w_W     = (const float*)d_in[17];
    const float* w_b     = (const float*)d_in[18];
    const float* bb_W    = (const float*)d_in[19];
    const float* bb_b    = (const float*)d_in[20];
    const float* ln_s    = (const float*)d_in[21];
    const float* ln_b    = (const float*)d_in[22];
    const float* rgb_W   = (const float*)d_in[23];
    const float* rgb_b   = (const float*)d_in[24];
    float* out = (float*)d_out;

    const int SMEM = 32 * 132 * 4 + 2 * 16384 + 256 * 8;   // 51712 B
    cudaFuncSetAttribute(decode_kernel,
                         cudaFuncAttributeMaxDynamicSharedMemorySize, SMEM);

    hyper_kernel<<<256, 256>>>(lat, temb, h_W0, h_b0, h_ln_s0, h_ln_b0,
                               w_W0, w_b0, bb_W0, bb_b0,
                               h_W, h_b, h_ln_s, h_ln_b,
                               w_W, w_b, bb_W, bb_b);
    decode_kernel<<<256, 256, SMEM>>>(rays, ln_s0, ln_b0, ln_s, ln_b,
                                      rgb_W, rgb_b, out);
}

// round 4
// speedup vs baseline: 3.9297x; 1.0956x over previous
#include <cuda_runtime.h>
#include <math.h>

// ---------------------------------------------------------------------------
// HyperNetworkDecoder: K=2, P=4096, 8 layers of width 64.
// hyper_kernel generates per-(k,layer) weights ONCE (chunk constant across P),
// written TRANSPOSED ([m][n]) for the decoder.  decode_kernel: all weights in
// smem (loaded once, single block barrier), warp-autonomous points with
// 16-lane shuffle LayerNorm, Q=2 points per thread.
// ---------------------------------------------------------------------------

#define KB 2

__device__ __align__(16) float g_W0[KB * 128 * 64];      // layer0 W^T [k][m pad128][n]
__device__ __align__(16) float g_Wl[KB * 7 * 64 * 64];   // layers 1..7 W^T [k][l-1][m][n]
__device__ __align__(16) float g_b [KB * 8 * 64];        // biases [k][l][n]

// ---------------------------------------------------------------------------
// Kernel 1: hypernetwork. grid = (k,l) x 16 output-splits = 256 blocks.
// ---------------------------------------------------------------------------
__global__ void __launch_bounds__(256) hyper_kernel(
    const float* __restrict__ latent_tokens,
    const float* __restrict__ token_embeddings,
    const float* __restrict__ h_W0,  const float* __restrict__ h_b0,
    const float* __restrict__ h_ln_s0, const float* __restrict__ h_ln_b0,
    const float* __restrict__ w_W0,  const float* __restrict__ w_b0,
    const float* __restrict__ bb_W0, const float* __restrict__ bb_b0,
    const float* __restrict__ h_W,   const float* __restrict__ h_b,
    const float* __restrict__ h_ln_s, const float* __restrict__ h_ln_b,
    const float* __restrict__ w_W,   const float* __restrict__ w_b,
    const float* __restrict__ bb_W,  const float* __restrict__ bb_b)
{
    __shared__ float chunk[128];
    __shared__ float part[4][64];
    __shared__ float pre[64];
    __shared__ float hbuf[64];

    const int tid = threadIdx.x;
    const int bx  = blockIdx.x;
    const int sp  = bx & 15;
    const int kl  = bx >> 4;
    const int k   = kl >> 3;
    const int l   = kl & 7;

    if (tid < 128)
        chunk[tid] = (tid < 64) ? latent_tokens[(k * 8 + l) * 64 + tid]
                                : token_embeddings[l * 64 + (tid - 64)];
    __syncthreads();

    const float* hWp = (l == 0) ? h_W0 : (h_W + (l - 1) * 128 * 64);
    {
        const int q = tid >> 6, j = tid & 63;
        float acc = 0.f;
        #pragma unroll
        for (int i = 0; i < 32; i++) {
            int ii = q * 32 + i;
            acc = fmaf(chunk[ii], __ldg(hWp + ii * 64 + j), acc);
        }
        part[q][j] = acc;
    }
    __syncthreads();
    if (tid < 64) {
        float hb = (l == 0) ? __ldg(h_b0 + tid) : __ldg(h_b + (l - 1) * 64 + tid);
        pre[tid] = part[0][tid] + part[1][tid] + part[2][tid] + part[3][tid] + hb;
    }
    __syncthreads();
    if (tid < 64) {
        float s1 = 0.f, s2 = 0.f;
        #pragma unroll 8
        for (int i = 0; i < 64; i++) { float v = pre[i]; s1 += v; s2 += v * v; }
        float mu   = s1 * (1.f / 64.f);
        float var  = s2 * (1.f / 64.f) - mu * mu;
        float rstd = rsqrtf(var + 1e-6f);
        float ls = (l == 0) ? __ldg(h_ln_s0 + tid) : __ldg(h_ln_s + (l - 1) * 64 + tid);
        float lb = (l == 0) ? __ldg(h_ln_b0 + tid) : __ldg(h_ln_b + (l - 1) * 64 + tid);
        float h  = fmaf((pre[tid] - mu) * rstd, ls, lb);
        hbuf[tid] = fmaxf(h, 0.f);
    }
    __syncthreads();

    const int OUT  = (l == 0) ? 8064 : 4096;
    const int CH   = OUT >> 4;
    const int o0   = sp * CH, oend = o0 + CH;
    const float* wWp = (l == 0) ? w_W0 : (w_W + (l - 1) * 64 * 4096);
    const float* wbp = (l == 0) ? w_b0 : (w_b + (l - 1) * 4096);

    float acc[2];
    #pragma unroll
    for (int i = 0; i < 2; i++) {
        int o = o0 + tid + i * 256;
        acc[i] = (o < oend) ? __ldg(wbp + o) : 0.f;
    }
    #pragma unroll 8
    for (int j = 0; j < 64; j++) {
        float hj = hbuf[j];
        const float* row = wWp + j * OUT;
        #pragma unroll
        for (int i = 0; i < 2; i++) {
            int o = o0 + tid + i * 256;
            if (o < oend) acc[i] = fmaf(hj, __ldg(row + o), acc[i]);
        }
    }
    // transposed writes: W^T[m][n]
    #pragma unroll
    for (int i = 0; i < 2; i++) {
        int o = o0 + tid + i * 256;
        if (o < oend) {
            if (l == 0) {
                int n = o / 126, m = o - n * 126;          // in=126
                g_W0[k * 8192 + m * 64 + n] = acc[i];
            } else {
                int n = o >> 6, m = o & 63;                // in=64
                g_Wl[k * 28672 + (l - 1) * 4096 + m * 64 + n] = acc[i];
            }
        }
    }

    if (sp == 0) {
        if (l == 0 && tid < 128)                            // zero pad rows m=126,127
            g_W0[k * 8192 + 8064 + tid] = 0.f;
        if (tid < 64) {
            const float* bWp = (l == 0) ? bb_W0 : (bb_W + (l - 1) * 64 * 64);
            float accb = (l == 0) ? __ldg(bb_b0 + tid) : __ldg(bb_b + (l - 1) * 64 + tid);
            #pragma unroll 8
            for (int j = 0; j < 64; j++)
                accb = fmaf(hbuf[j], __ldg(bWp + j * 64 + tid), accb);
            g_b[(k * 8 + l) * 64 + tid] = accb;
        }
    }
}

// ---------------------------------------------------------------------------
// Float-only accurate sin: 2-term Cody-Waite reduction by pi, then sinf.
// ---------------------------------------------------------------------------
__device__ __forceinline__ float acc_sin(float x)
{
    float q = rintf(x * 0.318309886183790672f);
    float r = fmaf(-q, 3.14159274101257324f, x);
    r = fmaf(-q, -8.74227800037e-8f, r);
    float s = sinf(r);
    return (((int)q) & 1) ? -s : s;
}

// acc4 += xs * w4 (scalar x vector)
#define FMAS4(A, XS, W) do { \
    (A).x = fmaf((XS), (W).x, (A).x); (A).y = fmaf((XS), (W).y, (A).y); \
    (A).z = fmaf((XS), (W).z, (A).z); (A).w = fmaf((XS), (W).w, (A).w); } while (0)

// ---------------------------------------------------------------------------
// Kernel 2: decoder. 128 blocks x 512 threads, 64 points/block (one k).
// Warp w owns points 4w..4w+3. Lane = (t in [0,16), c in {0,1}):
//   outputs [4t, 4t+4) of points pt0 = 4w+2c and pt1 = 4w+2c+1.
// All weights in smem ([m][n] transposed -> conflict-free float4 reads);
// single __syncthreads after load; per-layer sync is warp-local only.
// ---------------------------------------------------------------------------
__global__ void __launch_bounds__(512, 1) decode_kernel(
    const float* __restrict__ rays,
    const float* __restrict__ ln_s0, const float* __restrict__ ln_b0,
    const float* __restrict__ ln_s,  const float* __restrict__ ln_b,
    const float* __restrict__ rgb_W, const float* __restrict__ rgb_b,
    float* __restrict__ out)
{
    extern __shared__ float smem[];
    float4* sW0 = (float4*)smem;            // 2048 float4  (W0^T 128x64)
    float4* sWl = sW0 + 2048;               // 7168 float4  (7 x 64x64)
    float*  xs  = (float*)(sW0 + 9216);     // 64 rows * 132 floats

    const int tid  = threadIdx.x;
    const int w    = tid >> 5;
    const int lane = tid & 31;
    const int t    = lane & 15;
    const int c    = lane >> 4;
    const int n0   = t * 4;
    const int k    = blockIdx.x >> 6;

    const int pt0  = 4 * w + 2 * c;
    const int pt1  = pt0 + 1;
    const int gpt0 = blockIdx.x * 64 + pt0;

    // ---- weight load (coalesced, L2-hot) ----
    {
        const float4* s0 = (const float4*)g_W0 + k * 2048;
        const float4* s1 = (const float4*)g_Wl + k * 7168;
        #pragma unroll
        for (int i = 0; i < 4; i++) sW0[tid + i * 512] = __ldg(s0 + tid + i * 512);
        #pragma unroll
        for (int i = 0; i < 14; i++) sWl[tid + i * 512] = __ldg(s1 + tid + i * 512);
    }

    // ---- positional encoding (8 lanes per point: q = (lane>>3)&3, s = lane&7) ----
    {
        const int q  = (lane >> 3) & 3;
        const int s  = lane & 7;
        const int pp = 4 * w + q;
        float* xrow  = xs + pp * 132;
        const float* r = rays + (blockIdx.x * 64 + pp) * 6;
        float ox = __ldg(r + 0), oy = __ldg(r + 1), oz = __ldg(r + 2);
        float dx = __ldg(r + 3), dy = __ldg(r + 4), dz = __ldg(r + 5);
        float pl[6];
        pl[0] = dx; pl[1] = dy; pl[2] = dz;
        pl[3] = oy * dz - oz * dy;
        pl[4] = oz * dx - ox * dz;
        pl[5] = ox * dy - oy * dx;
        if (s == 7) {
            #pragma unroll
            for (int cm = 0; cm < 6; cm++) xrow[cm] = pl[cm];
            xrow[126] = 0.f; xrow[127] = 0.f;
        }
        const float PIH = 1.57079632679489662f;
        for (int f = s; f < 10; f += 8) {
            float fr = (float)(1 << f);
            #pragma unroll
            for (int cm = 0; cm < 6; cm++) {
                float a = pl[cm] * fr;
                xrow[6 + f * 6 + cm]  = acc_sin(a);
                xrow[66 + f * 6 + cm] = acc_sin(a + PIH);
            }
        }
    }
    __syncthreads();   // the ONLY block barrier

    const float*  bb  = g_b + k * 512;
    float*        xr0 = xs + pt0 * 132;
    float*        xr1 = xs + pt1 * 132;
    const float4* x40 = (const float4*)xr0;
    const float4* x41 = (const float4*)xr1;

    float4 a0, a1;

    #pragma unroll 1
    for (int l = 0; l < 8; l++) {
        const float4* Wt = (l == 0) ? sW0 : (sWl + (l - 1) * 1024);
        const int M4 = (l == 0) ? 32 : 16;

        float4 b4 = __ldg((const float4*)(bb + l * 64 + n0));
        a0 = b4; a1 = b4;

        #pragma unroll 8
        for (int m4 = 0; m4 < M4; m4++) {
            float4 x0 = x40[m4];
            float4 x1 = x41[m4];
            float4 w0 = Wt[(m4 * 4 + 0) * 16 + t];
            float4 w1 = Wt[(m4 * 4 + 1) * 16 + t];
            float4 w2 = Wt[(m4 * 4 + 2) * 16 + t];
            float4 w3 = Wt[(m4 * 4 + 3) * 16 + t];
            FMAS4(a0, x0.x, w0); FMAS4(a1, x1.x, w0);
            FMAS4(a0, x0.y, w1); FMAS4(a1, x1.y, w1);
            FMAS4(a0, x0.z, w2); FMAS4(a1, x1.z, w2);
            FMAS4(a0, x0.w, w3); FMAS4(a1, x1.w, w3);
        }

        // 16-lane shuffle LayerNorm (per point)
        float s10 = a0.x + a0.y + a0.z + a0.w;
        float s20 = a0.x * a0.x + a0.y * a0.y + a0.z * a0.z + a0.w * a0.w;
        float s11 = a1.x + a1.y + a1.z + a1.w;
        float s21 = a1.x * a1.x + a1.y * a1.y + a1.z * a1.z + a1.w * a1.w;
        #pragma unroll
        for (int m = 1; m < 16; m <<= 1) {
            s10 += __shfl_xor_sync(0xffffffffu, s10, m, 32);
            s20 += __shfl_xor_sync(0xffffffffu, s20, m, 32);
            s11 += __shfl_xor_sync(0xffffffffu, s11, m, 32);
            s21 += __shfl_xor_sync(0xffffffffu, s21, m, 32);
        }
        float mu0 = s10 * (1.f / 64.f);
        float mu1 = s11 * (1.f / 64.f);
        float rs0 = rsqrtf(s20 * (1.f / 64.f) - mu0 * mu0 + 1e-6f);
        float rs1 = rsqrtf(s21 * (1.f / 64.f) - mu1 * mu1 + 1e-6f);

        const float* lns = (l == 0) ? ln_s0 : (ln_s + (l - 1) * 64);
        const float* lnb = (l == 0) ? ln_b0 : (ln_b + (l - 1) * 64);
        float4 ls4 = __ldg((const float4*)(lns + n0));
        float4 lb4 = __ldg((const float4*)(lnb + n0));

        a0.x = fmaxf(fmaf((a0.x - mu0) * rs0, ls4.x, lb4.x), 0.f);
        a0.y = fmaxf(fmaf((a0.y - mu0) * rs0, ls4.y, lb4.y), 0.f);
        a0.z = fmaxf(fmaf((a0.z - mu0) * rs0, ls4.z, lb4.z), 0.f);
        a0.w = fmaxf(fmaf((a0.w - mu0) * rs0, ls4.w, lb4.w), 0.f);
        a1.x = fmaxf(fmaf((a1.x - mu1) * rs1, ls4.x, lb4.x), 0.f);
        a1.y = fmaxf(fmaf((a1.y - mu1) * rs1, ls4.y, lb4.y), 0.f);
        a1.z = fmaxf(fmaf((a1.z - mu1) * rs1, ls4.z, lb4.z), 0.f);
        a1.w = fmaxf(fmaf((a1.w - mu1) * rs1, ls4.w, lb4.w), 0.f);

        if (l < 7) {
            ((float4*)xr0)[t] = a0;
            ((float4*)xr1)[t] = a1;
            __syncwarp();
        }
    }

    // ---- rgb head + sigmoid (reduce 16 lanes via shuffle) ----
    {
        float r0[3], r1[3];
        #pragma unroll
        for (int cc = 0; cc < 3; cc++) { r0[cc] = 0.f; r1[cc] = 0.f; }
        #pragma unroll
        for (int j = 0; j < 4; j++) {
            float w0c = __ldg(rgb_W + (n0 + j) * 3 + 0);
            float w1c = __ldg(rgb_W + (n0 + j) * 3 + 1);
            float w2c = __ldg(rgb_W + (n0 + j) * 3 + 2);
            float v0 = (j == 0) ? a0.x : (j == 1) ? a0.y : (j == 2) ? a0.z : a0.w;
            float v1 = (j == 0) ? a1.x : (j == 1) ? a1.y : (j == 2) ? a1.z : a1.w;
            r0[0] = fmaf(v0, w0c, r0[0]); r1[0] = fmaf(v1, w0c, r1[0]);
            r0[1] = fmaf(v0, w1c, r0[1]); r1[1] = fmaf(v1, w1c, r1[1]);
            r0[2] = fmaf(v0, w2c, r0[2]); r1[2] = fmaf(v1, w2c, r1[2]);
        }
        #pragma unroll
        for (int m = 1; m < 16; m <<= 1) {
            #pragma unroll
            for (int cc = 0; cc < 3; cc++) {
                r0[cc] += __shfl_xor_sync(0xffffffffu, r0[cc], m, 32);
                r1[cc] += __shfl_xor_sync(0xffffffffu, r1[cc], m, 32);
            }
        }
        if (t == 0) {
            #pragma unroll
            for (int cc = 0; cc < 3; cc++) {
                float b = __ldg(rgb_b + cc);
                out[gpt0 * 3 + cc]       = 1.f / (1.f + expf(-(r0[cc] + b)));
                out[(gpt0 + 1) * 3 + cc] = 1.f / (1.f + expf(-(r1[cc] + b)));
            }
        }
    }
}

// ---------------------------------------------------------------------------
extern "C" void kernel_launch(void* const* d_in, const int* in_sizes, int n_in,
                              void* d_out, int out_size)
{
    const float* rays    = (const float*)d_in[0];
    const float* lat     = (const float*)d_in[1];
    const float* temb    = (const float*)d_in[2];
    const float* h_W0    = (const float*)d_in[3];
    const float* h_b0    = (const float*)d_in[4];
    const float* h_ln_s0 = (const float*)d_in[5];
    const float* h_ln_b0 = (const float*)d_in[6];
    const float* w_W0    = (const float*)d_in[7];
    const float* w_b0    = (const float*)d_in[8];
    const float* bb_W0   = (const float*)d_in[9];
    const float* bb_b0   = (const float*)d_in[10];
    const float* ln_s0   = (const float*)d_in[11];
    const float* ln_b0   = (const float*)d_in[12];
    const float* h_W     = (const float*)d_in[13];
    const float* h_b     = (const float*)d_in[14];
    const float* h_ln_s  = (const float*)d_in[15];
    const float* h_ln_b  = (const float*)d_in[16];
    const float* w_W     = (const float*)d_in[17];
    const float* w_b     = (const float*)d_in[18];
    const float* bb_W    = (const float*)d_in[19];
    const float* bb_b    = (const float*)d_in[20];
    const float* ln_s    = (const float*)d_in[21];
    const float* ln_b    = (const float*)d_in[22];
    const float* rgb_W   = (const float*)d_in[23];
    const float* rgb_b   = (const float*)d_in[24];
    float* out = (float*)d_out;

    const int SMEM = 9216 * 16 + 64 * 132 * 4;   // 181248 B
    cudaFuncSetAttribute(decode_kernel,
                         cudaFuncAttributeMaxDynamicSharedMemorySize, SMEM);

    hyper_kernel<<<256, 256>>>(lat, temb, h_W0, h_b0, h_ln_s0, h_ln_b0,
                               w_W0, w_b0, bb_W0, bb_b0,
                               h_W, h_b, h_ln_s, h_ln_b,
                               w_W, w_b, bb_W, bb_b);
    decode_kernel<<<128, 512, SMEM>>>(rays, ln_s0, ln_b0, ln_s, ln_b,
                                      rgb_W, rgb_b, out);
}